// round 11
// baseline (speedup 1.0000x reference)
#include <cuda_runtime.h>

#define NN 100000
#define NE 3200000
#define F  20
#define FP 24            // row = 96B = 6 float4: [h(20), as, ad, pad, pad]
#define SCAN_B 1024
#define NSCAN ((NN + SCAN_B - 1)/SCAN_B)   // 98
#define G 8

// ---------------- scratch (static __device__, zero-initialized at load) -----
__device__ int   g_rowptr[NN];    // segment start per node
__device__ int   g_rowend[NN];    // segment end per node
__device__ int   g_next[NN];      // hist counts, then scatter cursor; reset by agg2
__device__ int   g_csrsrc[NE];
__device__ __align__(16) float g_h[NN*FP];
__device__ float g_s[NN];         // layer1 softmax denom accum; reset by agg2
__device__ float g_S[NN];         // layer1 weighted-x accum;    reset by agg2
__device__ int   g_off;           // global segment offset counter; reset by agg2

__device__ __forceinline__ float lrelu(float v) { return v > 0.f ? v : 0.2f*v; }

// FMA-pipe exp. rel err ~2e-6.
__device__ __forceinline__ float fexp(float x) {
    x = fminf(fmaxf(x, -87.f), 87.f);
    float t = x * 1.4426950408889634f;
    float r = t + 12582912.0f;
    int   n = __float_as_int(r) - 0x4B400000;
    float f = t - (r - 12582912.0f);
    float p =            1.3333558e-3f;
    p = fmaf(p, f, 9.6181291e-3f);
    p = fmaf(p, f, 5.5504109e-2f);
    p = fmaf(p, f, 2.4022651e-1f);
    p = fmaf(p, f, 6.9314718e-1f);
    p = fmaf(p, f, 1.0f);
    return __int_as_float(__float_as_int(p) + (n << 23));
}

// ---------------- CSR build (stream A) ----------------
__global__ void k_hist(const int* __restrict__ dst) {
    int i = blockIdx.x*blockDim.x + threadIdx.x;   // NE/4 threads
    int4 dv = ((const int4*)dst)[i];
    atomicAdd(&g_next[dv.x], 1);
    atomicAdd(&g_next[dv.y], 1);
    atomicAdd(&g_next[dv.z], 1);
    atomicAdd(&g_next[dv.w], 1);
}

// single-pass offsets: block-local scan + atomic base grab (segments unordered)
__global__ void k_offsets() {
    __shared__ int wsum[32];
    __shared__ int sbase;
    int t = threadIdx.x;
    int lane = t & 31, warp = t >> 5;
    int i = blockIdx.x*SCAN_B + t;
    int c = (i < NN) ? g_next[i] : 0;
    int xv = c;
    #pragma unroll
    for (int off = 1; off < 32; off <<= 1) {
        int y = __shfl_up_sync(0xffffffffu, xv, off);
        if (lane >= off) xv += y;
    }
    if (lane == 31) wsum[warp] = xv;
    __syncthreads();
    if (warp == 0) {
        int w = wsum[lane];
        #pragma unroll
        for (int off = 1; off < 32; off <<= 1) {
            int y = __shfl_up_sync(0xffffffffu, w, off);
            if (lane >= off) w += y;
        }
        wsum[lane] = w;
    }
    __syncthreads();
    int incl = xv + (warp > 0 ? wsum[warp-1] : 0);
    if (t == SCAN_B-1) sbase = atomicAdd(&g_off, incl);  // block total
    __syncthreads();
    if (i < NN) {
        int start = sbase + incl - c;
        g_rowptr[i] = start;
        g_next[i]   = start;        // scatter cursor
        g_rowend[i] = start + c;
    }
}

__global__ void k_scatter(const int* __restrict__ src,
                          const int* __restrict__ dst) {
    int i = blockIdx.x*blockDim.x + threadIdx.x;
    int4 sv = ((const int4*)src)[i];
    int4 dv = ((const int4*)dst)[i];
    int p;
    p = atomicAdd(&g_next[dv.x], 1); g_csrsrc[p] = sv.x;
    p = atomicAdd(&g_next[dv.y], 1); g_csrsrc[p] = sv.y;
    p = atomicAdd(&g_next[dv.z], 1); g_csrsrc[p] = sv.z;
    p = atomicAdd(&g_next[dv.w], 1); g_csrsrc[p] = sv.w;
}

// ---------------- layer 1, edge-parallel with atomics (stream B) -----------
// w = exp(lrelu(xs*cs + xd*cd) - lrelu(xd*(cs+cd))); s[d]+=w; S[d]+=w*xs.
__global__ void k_l1edge(const float* __restrict__ x,
                         const int* __restrict__ src,
                         const int* __restrict__ dst,
                         const float* __restrict__ W1,
                         const float* __restrict__ as1,
                         const float* __restrict__ ad1) {
    float cs = 0.f, cd = 0.f;
    #pragma unroll
    for (int k = 0; k < F; k++) {
        float w1 = __ldg(&W1[k]);
        cs = fmaf(w1, __ldg(&as1[k]), cs);
        cd = fmaf(w1, __ldg(&ad1[k]), cd);
    }
    int i = blockIdx.x*blockDim.x + threadIdx.x;   // NE/4 threads
    int4 sv = ((const int4*)src)[i];
    int4 dv = ((const int4*)dst)[i];
    #pragma unroll
    for (int q = 0; q < 4; q++) {
        int sn = (q==0)?sv.x:(q==1)?sv.y:(q==2)?sv.z:sv.w;
        int dn = (q==0)?dv.x:(q==1)?dv.y:(q==2)?dv.z:dv.w;
        float xs = __ldg(&x[sn]);
        float xd = __ldg(&x[dn]);
        float w  = fexp(lrelu(fmaf(xs, cs, xd*cd)) - lrelu(xd*(cs+cd)));
        atomicAdd(&g_s[dn], w);
        atomicAdd(&g_S[dn], w*xs);
    }
}

// layer-1 normalize + relu + layer-2 node transform; writes g_h rows
__global__ void k_l1node(const float* __restrict__ x,
                         const float* __restrict__ W1,
                         const float* __restrict__ b1,
                         const float* __restrict__ W2,
                         const float* __restrict__ as2,
                         const float* __restrict__ ad2) {
    __shared__ float sW1[F], sB1[F], sW2[F*F], sA2[F], sD2[F];
    int t = threadIdx.x;
    for (int k = t; k < F; k += blockDim.x) {
        sW1[k] = W1[k]; sB1[k] = b1[k]; sA2[k] = as2[k]; sD2[k] = ad2[k];
    }
    for (int k = t; k < F*F; k += blockDim.x) sW2[k] = W2[k];
    __syncthreads();

    int gid = blockIdx.x*blockDim.x + t;   // grid = NN*G exactly
    int d = gid / G, sub = gid & (G-1);
    unsigned gmask = 0xffu << ((t & 31) & ~7);

    float xd = x[d];
    float s  = g_s[d] + 1.f;        // + self-loop (w = 1)
    float S  = g_S[d] + xd;
    float val = S / (s + 1e-16f);

    float feat[F];
    #pragma unroll
    for (int k = 0; k < F; k++) feat[k] = fmaxf(fmaf(sW1[k], val, sB1[k]), 0.f);

    float csp = 0.f, cdp = 0.f;
    float* row = &g_h[d*FP];
    #pragma unroll
    for (int r = 0; r < 3; r++) {
        int j = sub + 8*r;
        if (j < F) {
            float h2 = 0.f;
            #pragma unroll
            for (int k = 0; k < F; k++) h2 = fmaf(feat[k], sW2[k*F + j], h2);
            row[j] = h2;
            csp = fmaf(h2, sA2[j], csp);
            cdp = fmaf(h2, sD2[j], cdp);
        }
    }
    #pragma unroll
    for (int off = G/2; off > 0; off >>= 1) {
        csp += __shfl_xor_sync(gmask, csp, off, G);
        cdp += __shfl_xor_sync(gmask, cdp, off, G);
    }
    if (sub == 0) { row[F] = csp; row[F+1] = cdp; }
}

// ---------------- layer 2 aggregation + final linear (after join) ----------
// Also resets g_next/g_s/g_S/g_off for the NEXT call (keeps every call identical).
__global__ void k_agg2(const float* __restrict__ b,
                       const float* __restrict__ Wl,
                       const float* __restrict__ bl,
                       float* __restrict__ out) {
    int gid = blockIdx.x*blockDim.x + threadIdx.x;
    // reset scratch for next launch
    if (gid < NN) { g_next[gid] = 0; g_s[gid] = 0.f; g_S[gid] = 0.f; }
    if (gid == 0) g_off = 0;

    int d = gid / G, sub = gid & (G-1);
    unsigned gmask = 0xffu << ((threadIdx.x & 31) & ~7);
    bool ld = sub < 6;

    const float4* rows = (const float4*)g_h;

    float4 v0 = ld ? rows[d*6 + sub] : make_float4(0.f,0.f,0.f,0.f);
    float add = __shfl_sync(gmask, v0.y, 5, G);
    float m0  = lrelu(__shfl_sync(gmask, v0.x, 5, G) + add);
    float s = 1.f;
    float a0 = v0.x, a1 = v0.y, a2 = v0.z, a3 = v0.w;

    int beg = g_rowptr[d], end = g_rowend[d];
    int j = beg;
    for (; j + 1 < end; j += 2) {
        int sn0 = g_csrsrc[j];
        int sn1 = g_csrsrc[j+1];
        float4 va = ld ? rows[sn0*6 + sub] : make_float4(0.f,0.f,0.f,0.f);
        float4 vb = ld ? rows[sn1*6 + sub] : make_float4(0.f,0.f,0.f,0.f);
        float wa = fexp(lrelu(__shfl_sync(gmask, va.x, 5, G) + add) - m0);
        float wb = fexp(lrelu(__shfl_sync(gmask, vb.x, 5, G) + add) - m0);
        s += wa + wb;
        a0 = fmaf(wa, va.x, a0); a1 = fmaf(wa, va.y, a1);
        a2 = fmaf(wa, va.z, a2); a3 = fmaf(wa, va.w, a3);
        a0 = fmaf(wb, vb.x, a0); a1 = fmaf(wb, vb.y, a1);
        a2 = fmaf(wb, vb.z, a2); a3 = fmaf(wb, vb.w, a3);
    }
    if (j < end) {
        int sn0 = g_csrsrc[j];
        float4 va = ld ? rows[sn0*6 + sub] : make_float4(0.f,0.f,0.f,0.f);
        float wa = fexp(lrelu(__shfl_sync(gmask, va.x, 5, G) + add) - m0);
        s += wa;
        a0 = fmaf(wa, va.x, a0); a1 = fmaf(wa, va.y, a1);
        a2 = fmaf(wa, va.z, a2); a3 = fmaf(wa, va.w, a3);
    }

    float inv = 1.f/(s + 1e-16f);
    float o = 0.f;
    if (sub < 5) {
        int c = 4*sub;
        o  = fmaxf(fmaf(a0, inv, b[c+0]*0.f + b[c+0]), 0.f) * Wl[c+0];
        // (kept simple below; above line replaced)
        o  = fmaxf(a0*inv + b[c+0], 0.f) * Wl[c+0];
        o += fmaxf(a1*inv + b[c+1], 0.f) * Wl[c+1];
        o += fmaxf(a2*inv + b[c+2], 0.f) * Wl[c+2];
        o += fmaxf(a3*inv + b[c+3], 0.f) * Wl[c+3];
    }
    #pragma unroll
    for (int off = G/2; off > 0; off >>= 1)
        o += __shfl_xor_sync(gmask, o, off, G);
    if (sub == 0) out[d] = o + bl[0];
}

// ---------------- streams for fork/join (created at load; no device mem) ----
static cudaStream_t s_b = 0;
static cudaEvent_t  e_fork = 0, e_join = 0;
static bool s_ok = false;
namespace {
struct StreamInit {
    StreamInit() {
        s_ok = (cudaStreamCreateWithFlags(&s_b, cudaStreamNonBlocking) == cudaSuccess)
            && (cudaEventCreateWithFlags(&e_fork, cudaEventDisableTiming) == cudaSuccess)
            && (cudaEventCreateWithFlags(&e_join, cudaEventDisableTiming) == cudaSuccess);
    }
} s_init;
}

// ---------------- launch ----------------
extern "C" void kernel_launch(void* const* d_in, const int* in_sizes, int n_in,
                              void* d_out, int out_size) {
    const float* x   = (const float*)d_in[0];
    const int*   ei  = (const int*)d_in[1];
    const float* W1  = (const float*)d_in[2];
    const float* as1 = (const float*)d_in[3];
    const float* ad1 = (const float*)d_in[4];
    const float* b1  = (const float*)d_in[5];
    const float* W2  = (const float*)d_in[6];
    const float* as2 = (const float*)d_in[7];
    const float* ad2 = (const float*)d_in[8];
    const float* b2  = (const float*)d_in[9];
    const float* Wl  = (const float*)d_in[10];
    const float* bl  = (const float*)d_in[11];
    float* out = (float*)d_out;

    const int* src = ei;
    const int* dst = ei + NE;

    int gE4 = (NE/4)/256;        // 3125
    int gA  = (NN*G)/256;        // 3125

    if (s_ok) {
        // fork: layer-1 chain on stream B (independent of CSR)
        cudaEventRecord(e_fork, 0);
        cudaStreamWaitEvent(s_b, e_fork, 0);
        k_l1edge<<<gE4, 256, 0, s_b>>>(x, src, dst, W1, as1, ad1);
        k_l1node<<<gA, 256, 0, s_b>>>(x, W1, b1, W2, as2, ad2);
        cudaEventRecord(e_join, s_b);

        // stream A (default): CSR build
        k_hist   <<<gE4, 256>>>(dst);
        k_offsets<<<NSCAN, SCAN_B>>>();
        k_scatter<<<gE4, 256>>>(src, dst);

        // join, then layer-2 aggregation + head
        cudaStreamWaitEvent(0, e_join, 0);
        k_agg2<<<gA, 256>>>(b2, Wl, bl, out);
    } else {
        // serial fallback (same semantics)
        k_l1edge<<<gE4, 256>>>(x, src, dst, W1, as1, ad1);
        k_l1node<<<gA, 256>>>(x, W1, b1, W2, as2, ad2);
        k_hist   <<<gE4, 256>>>(dst);
        k_offsets<<<NSCAN, SCAN_B>>>();
        k_scatter<<<gE4, 256>>>(src, dst);
        k_agg2<<<gA, 256>>>(b2, Wl, bl, out);
    }
}

// round 12
// speedup vs baseline: 1.2080x; 1.2080x over previous
#include <cuda_runtime.h>

#define NN 100000
#define NE 3200000
#define F  20
#define FP 24            // row = 96B = 6 float4: [h(20), as, ad, pad, pad]
#define SCAN_B 1024
#define NSCAN ((NN + SCAN_B - 1)/SCAN_B)   // 98
#define G 8

// ---------------- scratch (static __device__, zero-initialized at load) -----
__device__ int   g_rowptr[NN];    // segment start per node
__device__ int   g_rowend[NN];    // segment end per node
__device__ int   g_next[NN];      // hist counts -> scatter cursor; reset by agg2
__device__ int   g_csrsrc[NE];
__device__ __align__(16) float g_h[NN*FP];
__device__ int   g_off;           // global segment offset counter; reset by agg2

__device__ __forceinline__ float lrelu(float v) { return v > 0.f ? v : 0.2f*v; }

// FMA-pipe exp. rel err ~2e-6.
__device__ __forceinline__ float fexp(float x) {
    x = fminf(fmaxf(x, -87.f), 87.f);
    float t = x * 1.4426950408889634f;
    float r = t + 12582912.0f;
    int   n = __float_as_int(r) - 0x4B400000;
    float f = t - (r - 12582912.0f);
    float p =            1.3333558e-3f;
    p = fmaf(p, f, 9.6181291e-3f);
    p = fmaf(p, f, 5.5504109e-2f);
    p = fmaf(p, f, 2.4022651e-1f);
    p = fmaf(p, f, 6.9314718e-1f);
    p = fmaf(p, f, 1.0f);
    return __int_as_float(__float_as_int(p) + (n << 23));
}

// ---------------- CSR build ----------------
__global__ void k_hist(const int* __restrict__ dst) {
    int i = blockIdx.x*blockDim.x + threadIdx.x;   // NE/4 threads
    int4 dv = ((const int4*)dst)[i];
    atomicAdd(&g_next[dv.x], 1);
    atomicAdd(&g_next[dv.y], 1);
    atomicAdd(&g_next[dv.z], 1);
    atomicAdd(&g_next[dv.w], 1);
}

// single-pass offsets: block-local scan + atomic base grab (segments unordered)
__global__ void k_offsets() {
    __shared__ int wsum[32];
    __shared__ int sbase;
    int t = threadIdx.x;
    int lane = t & 31, warp = t >> 5;
    int i = blockIdx.x*SCAN_B + t;
    int c = (i < NN) ? g_next[i] : 0;
    int xv = c;
    #pragma unroll
    for (int off = 1; off < 32; off <<= 1) {
        int y = __shfl_up_sync(0xffffffffu, xv, off);
        if (lane >= off) xv += y;
    }
    if (lane == 31) wsum[warp] = xv;
    __syncthreads();
    if (warp == 0) {
        int w = wsum[lane];
        #pragma unroll
        for (int off = 1; off < 32; off <<= 1) {
            int y = __shfl_up_sync(0xffffffffu, w, off);
            if (lane >= off) w += y;
        }
        wsum[lane] = w;
    }
    __syncthreads();
    int incl = xv + (warp > 0 ? wsum[warp-1] : 0);
    if (t == SCAN_B-1) sbase = atomicAdd(&g_off, incl);  // grab base for block
    __syncthreads();
    if (i < NN) {
        int start = sbase + incl - c;
        g_rowptr[i] = start;
        g_next[i]   = start;        // scatter cursor
        g_rowend[i] = start + c;
    }
}

__global__ void k_scatter(const int* __restrict__ src,
                          const int* __restrict__ dst) {
    int i = blockIdx.x*blockDim.x + threadIdx.x;
    int4 sv = ((const int4*)src)[i];
    int4 dv = ((const int4*)dst)[i];
    int p;
    p = atomicAdd(&g_next[dv.x], 1); g_csrsrc[p] = sv.x;
    p = atomicAdd(&g_next[dv.y], 1); g_csrsrc[p] = sv.y;
    p = atomicAdd(&g_next[dv.z], 1); g_csrsrc[p] = sv.z;
    p = atomicAdd(&g_next[dv.w], 1); g_csrsrc[p] = sv.w;
}

// ---------------- layer 1 aggregation + layer 2 node transform -------------
// Per edge: gather ONLY x[src] (4B); softmax shifted by self-loop logit.
__global__ void k_l1(const float* __restrict__ x,
                     const float* __restrict__ W1,
                     const float* __restrict__ as1,
                     const float* __restrict__ ad1,
                     const float* __restrict__ b1,
                     const float* __restrict__ W2,
                     const float* __restrict__ as2,
                     const float* __restrict__ ad2) {
    __shared__ float sW1[F], sB1[F], sW2[F*F], sA2[F], sD2[F];
    int t = threadIdx.x;
    for (int k = t; k < F; k += blockDim.x) {
        sW1[k] = W1[k]; sB1[k] = b1[k]; sA2[k] = as2[k]; sD2[k] = ad2[k];
    }
    for (int k = t; k < F*F; k += blockDim.x) sW2[k] = W2[k];
    __syncthreads();

    float cs = 0.f, cd = 0.f;
    #pragma unroll
    for (int k = 0; k < F; k++) { cs += sW1[k]*as1[k]; cd += sW1[k]*ad1[k]; }

    int gid = blockIdx.x*blockDim.x + t;   // grid = NN*G exactly
    int d = gid / G, sub = gid & (G-1);
    unsigned gmask = 0xffu << ((t & 31) & ~7);

    float xd  = x[d];
    float add = xd * cd;
    float m0  = lrelu(xd*cs + add);
    float s = (sub == 0) ? 1.f : 0.f;
    float S = (sub == 0) ? xd  : 0.f;

    int beg = g_rowptr[d], end = g_rowend[d];
    for (int j = beg + sub; j < end; j += G) {
        float xs = x[g_csrsrc[j]];
        float w  = fexp(lrelu(xs*cs + add) - m0);
        s += w;
        S = fmaf(w, xs, S);
    }
    #pragma unroll
    for (int off = G/2; off > 0; off >>= 1) {
        s += __shfl_xor_sync(gmask, s, off, G);
        S += __shfl_xor_sync(gmask, S, off, G);
    }
    float val = S / (s + 1e-16f);

    float feat[F];
    #pragma unroll
    for (int k = 0; k < F; k++) feat[k] = fmaxf(fmaf(sW1[k], val, sB1[k]), 0.f);

    float csp = 0.f, cdp = 0.f;
    float* row = &g_h[d*FP];
    #pragma unroll
    for (int r = 0; r < 3; r++) {
        int j = sub + 8*r;
        if (j < F) {
            float h2 = 0.f;
            #pragma unroll
            for (int k = 0; k < F; k++) h2 = fmaf(feat[k], sW2[k*F + j], h2);
            row[j] = h2;
            csp = fmaf(h2, sA2[j], csp);
            cdp = fmaf(h2, sD2[j], cdp);
        }
    }
    #pragma unroll
    for (int off = G/2; off > 0; off >>= 1) {
        csp += __shfl_xor_sync(gmask, csp, off, G);
        cdp += __shfl_xor_sync(gmask, cdp, off, G);
    }
    if (sub == 0) { row[F] = csp; row[F+1] = cdp; }
}

// ---------------- layer 2 aggregation + final linear -----------------------
// COOPERATIVE: 8-lane group per dst; lanes 0-5 load one float4 of each 96B row
// (coalesced). Resets g_next/g_off for the NEXT call (identical work per call).
__global__ void k_agg2(const float* __restrict__ b,
                       const float* __restrict__ Wl,
                       const float* __restrict__ bl,
                       float* __restrict__ out) {
    int gid = blockIdx.x*blockDim.x + threadIdx.x;
    if (gid < NN) g_next[gid] = 0;      // reset for next call's hist
    if (gid == 0) g_off = 0;

    int d = gid / G, sub = gid & (G-1);
    unsigned gmask = 0xffu << ((threadIdx.x & 31) & ~7);
    bool ld = sub < 6;

    const float4* rows = (const float4*)g_h;

    float4 v0 = ld ? rows[d*6 + sub] : make_float4(0.f,0.f,0.f,0.f);
    float add = __shfl_sync(gmask, v0.y, 5, G);     // ad of dst
    float m0  = lrelu(__shfl_sync(gmask, v0.x, 5, G) + add);
    float s = 1.f;
    float a0 = v0.x, a1 = v0.y, a2 = v0.z, a3 = v0.w;

    int beg = g_rowptr[d], end = g_rowend[d];
    int j = beg;
    for (; j + 1 < end; j += 2) {
        int sn0 = g_csrsrc[j];
        int sn1 = g_csrsrc[j+1];
        float4 va = ld ? rows[sn0*6 + sub] : make_float4(0.f,0.f,0.f,0.f);
        float4 vb = ld ? rows[sn1*6 + sub] : make_float4(0.f,0.f,0.f,0.f);
        float wa = fexp(lrelu(__shfl_sync(gmask, va.x, 5, G) + add) - m0);
        float wb = fexp(lrelu(__shfl_sync(gmask, vb.x, 5, G) + add) - m0);
        s += wa + wb;
        a0 = fmaf(wa, va.x, a0); a1 = fmaf(wa, va.y, a1);
        a2 = fmaf(wa, va.z, a2); a3 = fmaf(wa, va.w, a3);
        a0 = fmaf(wb, vb.x, a0); a1 = fmaf(wb, vb.y, a1);
        a2 = fmaf(wb, vb.z, a2); a3 = fmaf(wb, vb.w, a3);
    }
    if (j < end) {
        int sn0 = g_csrsrc[j];
        float4 va = ld ? rows[sn0*6 + sub] : make_float4(0.f,0.f,0.f,0.f);
        float wa = fexp(lrelu(__shfl_sync(gmask, va.x, 5, G) + add) - m0);
        s += wa;
        a0 = fmaf(wa, va.x, a0); a1 = fmaf(wa, va.y, a1);
        a2 = fmaf(wa, va.z, a2); a3 = fmaf(wa, va.w, a3);
    }

    // lanes 0..4 hold feature cols 4*sub .. 4*sub+3
    float inv = 1.f/(s + 1e-16f);
    float o = 0.f;
    if (sub < 5) {
        int c = 4*sub;
        o  = fmaxf(a0*inv + b[c+0], 0.f) * Wl[c+0];
        o += fmaxf(a1*inv + b[c+1], 0.f) * Wl[c+1];
        o += fmaxf(a2*inv + b[c+2], 0.f) * Wl[c+2];
        o += fmaxf(a3*inv + b[c+3], 0.f) * Wl[c+3];
    }
    #pragma unroll
    for (int off = G/2; off > 0; off >>= 1)
        o += __shfl_xor_sync(gmask, o, off, G);
    if (sub == 0) out[d] = o + bl[0];
}

// ---------------- launch ----------------
extern "C" void kernel_launch(void* const* d_in, const int* in_sizes, int n_in,
                              void* d_out, int out_size) {
    const float* x   = (const float*)d_in[0];
    const int*   ei  = (const int*)d_in[1];
    const float* W1  = (const float*)d_in[2];
    const float* as1 = (const float*)d_in[3];
    const float* ad1 = (const float*)d_in[4];
    const float* b1  = (const float*)d_in[5];
    const float* W2  = (const float*)d_in[6];
    const float* as2 = (const float*)d_in[7];
    const float* ad2 = (const float*)d_in[8];
    const float* b2  = (const float*)d_in[9];
    const float* Wl  = (const float*)d_in[10];
    const float* bl  = (const float*)d_in[11];
    float* out = (float*)d_out;

    const int* src = ei;
    const int* dst = ei + NE;

    int gE4 = (NE/4)/256;        // 3125
    int gA  = (NN*G)/256;        // 3125

    k_hist   <<<gE4, 256>>>(dst);
    k_offsets<<<NSCAN, SCAN_B>>>();
    k_scatter<<<gE4, 256>>>(src, dst);

    k_l1  <<<gA, 256>>>(x, W1, as1, ad1, b1, W2, as2, ad2);
    k_agg2<<<gA, 256>>>(b2, Wl, bl, out);
}

// round 13
// speedup vs baseline: 1.2318x; 1.0197x over previous
#include <cuda_runtime.h>

#define NN 100000
#define NE 3200000
#define F  20
#define FP 24            // row = 96B = 6 float4: [h(20), as, ad, pad, pad]
#define SCAN_B 1024
#define NSCAN ((NN + SCAN_B - 1)/SCAN_B)   // 98
#define G 8

// ---------------- scratch (static __device__, zero-initialized at load) -----
__device__ int   g_rowptr[NN];    // segment start per node
__device__ int   g_rowend[NN];    // segment end per node
__device__ int   g_next[NN];      // hist counts -> scatter cursor; reset by agg2
__device__ __align__(16) int2  g_edge[NE];   // {src, x[src] bits}
__device__ __align__(16) float g_h[NN*FP];
__device__ int   g_off;           // global segment offset counter; reset by agg2

__device__ __forceinline__ float lrelu(float v) { return v > 0.f ? v : 0.2f*v; }

// FMA-pipe exp. rel err ~2e-6.
__device__ __forceinline__ float fexp(float x) {
    x = fminf(fmaxf(x, -87.f), 87.f);
    float t = x * 1.4426950408889634f;
    float r = t + 12582912.0f;
    int   n = __float_as_int(r) - 0x4B400000;
    float f = t - (r - 12582912.0f);
    float p =            1.3333558e-3f;
    p = fmaf(p, f, 9.6181291e-3f);
    p = fmaf(p, f, 5.5504109e-2f);
    p = fmaf(p, f, 2.4022651e-1f);
    p = fmaf(p, f, 6.9314718e-1f);
    p = fmaf(p, f, 1.0f);
    return __int_as_float(__float_as_int(p) + (n << 23));
}

// ---------------- CSR build ----------------
__global__ void k_hist(const int* __restrict__ dst) {
    int i = blockIdx.x*blockDim.x + threadIdx.x;   // NE/4 threads
    int4 dv = ((const int4*)dst)[i];
    atomicAdd(&g_next[dv.x], 1);
    atomicAdd(&g_next[dv.y], 1);
    atomicAdd(&g_next[dv.z], 1);
    atomicAdd(&g_next[dv.w], 1);
}

// single-pass offsets: block-local scan + atomic base grab (segments unordered)
__global__ void k_offsets() {
    __shared__ int wsum[32];
    __shared__ int sbase;
    int t = threadIdx.x;
    int lane = t & 31, warp = t >> 5;
    int i = blockIdx.x*SCAN_B + t;
    int c = (i < NN) ? g_next[i] : 0;
    int xv = c;
    #pragma unroll
    for (int off = 1; off < 32; off <<= 1) {
        int y = __shfl_up_sync(0xffffffffu, xv, off);
        if (lane >= off) xv += y;
    }
    if (lane == 31) wsum[warp] = xv;
    __syncthreads();
    if (warp == 0) {
        int w = wsum[lane];
        #pragma unroll
        for (int off = 1; off < 32; off <<= 1) {
            int y = __shfl_up_sync(0xffffffffu, w, off);
            if (lane >= off) w += y;
        }
        wsum[lane] = w;
    }
    __syncthreads();
    int incl = xv + (warp > 0 ? wsum[warp-1] : 0);
    if (t == SCAN_B-1) sbase = atomicAdd(&g_off, incl);
    __syncthreads();
    if (i < NN) {
        int start = sbase + incl - c;
        g_rowptr[i] = start;
        g_next[i]   = start;        // scatter cursor
        g_rowend[i] = start + c;
    }
}

// scatter edge records {src, x[src]}: the x-gather hides under atomic latency,
// and the 8B random store costs the same 32B sector as the old 4B store.
__global__ void k_scatter(const int* __restrict__ src,
                          const int* __restrict__ dst,
                          const float* __restrict__ x) {
    int i = blockIdx.x*blockDim.x + threadIdx.x;   // NE/4 threads
    int4 sv = ((const int4*)src)[i];
    int4 dv = ((const int4*)dst)[i];
    float x0 = __ldg(&x[sv.x]);
    float x1 = __ldg(&x[sv.y]);
    float x2 = __ldg(&x[sv.z]);
    float x3 = __ldg(&x[sv.w]);
    int p;
    p = atomicAdd(&g_next[dv.x], 1); g_edge[p] = make_int2(sv.x, __float_as_int(x0));
    p = atomicAdd(&g_next[dv.y], 1); g_edge[p] = make_int2(sv.y, __float_as_int(x1));
    p = atomicAdd(&g_next[dv.z], 1); g_edge[p] = make_int2(sv.z, __float_as_int(x2));
    p = atomicAdd(&g_next[dv.w], 1); g_edge[p] = make_int2(sv.w, __float_as_int(x3));
}

// ---------------- layer 1 aggregation + layer 2 node transform -------------
// Per edge: read x_src from the edge record (COALESCED, no gather).
__global__ void k_l1(const float* __restrict__ x,
                     const float* __restrict__ W1,
                     const float* __restrict__ as1,
                     const float* __restrict__ ad1,
                     const float* __restrict__ b1,
                     const float* __restrict__ W2,
                     const float* __restrict__ as2,
                     const float* __restrict__ ad2) {
    __shared__ float sW1[F], sB1[F], sW2[F*F], sA2[F], sD2[F];
    int t = threadIdx.x;
    for (int k = t; k < F; k += blockDim.x) {
        sW1[k] = W1[k]; sB1[k] = b1[k]; sA2[k] = as2[k]; sD2[k] = ad2[k];
    }
    for (int k = t; k < F*F; k += blockDim.x) sW2[k] = W2[k];
    __syncthreads();

    float cs = 0.f, cd = 0.f;
    #pragma unroll
    for (int k = 0; k < F; k++) { cs += sW1[k]*as1[k]; cd += sW1[k]*ad1[k]; }

    int gid = blockIdx.x*blockDim.x + t;   // grid = NN*G exactly
    int d = gid / G, sub = gid & (G-1);
    unsigned gmask = 0xffu << ((t & 31) & ~7);

    float xd  = x[d];
    float add = xd * cd;
    float m0  = lrelu(xd*cs + add);
    float s = (sub == 0) ? 1.f : 0.f;
    float S = (sub == 0) ? xd  : 0.f;

    int beg = g_rowptr[d], end = g_rowend[d];
    for (int j = beg + sub; j < end; j += G) {
        float xs = __int_as_float(g_edge[j].y);    // coalesced stream
        float w  = fexp(lrelu(xs*cs + add) - m0);
        s += w;
        S = fmaf(w, xs, S);
    }
    #pragma unroll
    for (int off = G/2; off > 0; off >>= 1) {
        s += __shfl_xor_sync(gmask, s, off, G);
        S += __shfl_xor_sync(gmask, S, off, G);
    }
    float val = S / (s + 1e-16f);

    float feat[F];
    #pragma unroll
    for (int k = 0; k < F; k++) feat[k] = fmaxf(fmaf(sW1[k], val, sB1[k]), 0.f);

    float csp = 0.f, cdp = 0.f;
    float* row = &g_h[d*FP];
    #pragma unroll
    for (int r = 0; r < 3; r++) {
        int j = sub + 8*r;
        if (j < F) {
            float h2 = 0.f;
            #pragma unroll
            for (int k = 0; k < F; k++) h2 = fmaf(feat[k], sW2[k*F + j], h2);
            row[j] = h2;
            csp = fmaf(h2, sA2[j], csp);
            cdp = fmaf(h2, sD2[j], cdp);
        }
    }
    #pragma unroll
    for (int off = G/2; off > 0; off >>= 1) {
        csp += __shfl_xor_sync(gmask, csp, off, G);
        cdp += __shfl_xor_sync(gmask, cdp, off, G);
    }
    if (sub == 0) { row[F] = csp; row[F+1] = cdp; }
}

// ---------------- layer 2 aggregation + final linear -----------------------
// COOPERATIVE: 8-lane group per dst; lanes 0-5 load one float4 of each 96B row.
// Resets g_next/g_off for the NEXT call (identical work every call).
__global__ void k_agg2(const float* __restrict__ b,
                       const float* __restrict__ Wl,
                       const float* __restrict__ bl,
                       float* __restrict__ out) {
    int gid = blockIdx.x*blockDim.x + threadIdx.x;
    if (gid < NN) g_next[gid] = 0;
    if (gid == 0) g_off = 0;

    int d = gid / G, sub = gid & (G-1);
    unsigned gmask = 0xffu << ((threadIdx.x & 31) & ~7);
    bool ld = sub < 6;

    const float4* rows = (const float4*)g_h;

    float4 v0 = ld ? rows[d*6 + sub] : make_float4(0.f,0.f,0.f,0.f);
    float add = __shfl_sync(gmask, v0.y, 5, G);     // ad of dst
    float m0  = lrelu(__shfl_sync(gmask, v0.x, 5, G) + add);
    float s = 1.f;
    float a0 = v0.x, a1 = v0.y, a2 = v0.z, a3 = v0.w;

    int beg = g_rowptr[d], end = g_rowend[d];
    int j = beg;
    for (; j + 1 < end; j += 2) {
        int sn0 = g_edge[j].x;
        int sn1 = g_edge[j+1].x;
        float4 va = ld ? rows[sn0*6 + sub] : make_float4(0.f,0.f,0.f,0.f);
        float4 vb = ld ? rows[sn1*6 + sub] : make_float4(0.f,0.f,0.f,0.f);
        float wa = fexp(lrelu(__shfl_sync(gmask, va.x, 5, G) + add) - m0);
        float wb = fexp(lrelu(__shfl_sync(gmask, vb.x, 5, G) + add) - m0);
        s += wa + wb;
        a0 = fmaf(wa, va.x, a0); a1 = fmaf(wa, va.y, a1);
        a2 = fmaf(wa, va.z, a2); a3 = fmaf(wa, va.w, a3);
        a0 = fmaf(wb, vb.x, a0); a1 = fmaf(wb, vb.y, a1);
        a2 = fmaf(wb, vb.z, a2); a3 = fmaf(wb, vb.w, a3);
    }
    if (j < end) {
        int sn0 = g_edge[j].x;
        float4 va = ld ? rows[sn0*6 + sub] : make_float4(0.f,0.f,0.f,0.f);
        float wa = fexp(lrelu(__shfl_sync(gmask, va.x, 5, G) + add) - m0);
        s += wa;
        a0 = fmaf(wa, va.x, a0); a1 = fmaf(wa, va.y, a1);
        a2 = fmaf(wa, va.z, a2); a3 = fmaf(wa, va.w, a3);
    }

    float inv = 1.f/(s + 1e-16f);
    float o = 0.f;
    if (sub < 5) {
        int c = 4*sub;
        o  = fmaxf(a0*inv + b[c+0], 0.f) * Wl[c+0];
        o += fmaxf(a1*inv + b[c+1], 0.f) * Wl[c+1];
        o += fmaxf(a2*inv + b[c+2], 0.f) * Wl[c+2];
        o += fmaxf(a3*inv + b[c+3], 0.f) * Wl[c+3];
    }
    #pragma unroll
    for (int off = G/2; off > 0; off >>= 1)
        o += __shfl_xor_sync(gmask, o, off, G);
    if (sub == 0) out[d] = o + bl[0];
}

// ---------------- launch ----------------
extern "C" void kernel_launch(void* const* d_in, const int* in_sizes, int n_in,
                              void* d_out, int out_size) {
    const float* x   = (const float*)d_in[0];
    const int*   ei  = (const int*)d_in[1];
    const float* W1  = (const float*)d_in[2];
    const float* as1 = (const float*)d_in[3];
    const float* ad1 = (const float*)d_in[4];
    const float* b1  = (const float*)d_in[5];
    const float* W2  = (const float*)d_in[6];
    const float* as2 = (const float*)d_in[7];
    const float* ad2 = (const float*)d_in[8];
    const float* b2  = (const float*)d_in[9];
    const float* Wl  = (const float*)d_in[10];
    const float* bl  = (const float*)d_in[11];
    float* out = (float*)d_out;

    const int* src = ei;
    const int* dst = ei + NE;

    int gE4 = (NE/4)/256;        // 3125
    int gA  = (NN*G)/256;        // 3125

    k_hist   <<<gE4, 256>>>(dst);
    k_offsets<<<NSCAN, SCAN_B>>>();
    k_scatter<<<gE4, 256>>>(src, dst, x);

    k_l1  <<<gA, 256>>>(x, W1, as1, ad1, b1, W2, as2, ad2);
    k_agg2<<<gA, 256>>>(b2, Wl, bl, out);
}